// round 1
// baseline (speedup 1.0000x reference)
#include <cuda_runtime.h>

// ---------------------------------------------------------------------------
// My_loss: masked sum over N of  |oP - tP| + 1.9 * |V*drho_mix_dp(0.1*oP)*dpdt - mdot|
// Pure HBM-bound streaming reduction: 4 float32 arrays of N=8M in, 1 float out.
// ---------------------------------------------------------------------------

#define TPB     256
#define NBLOCKS 2048

__device__ double g_partials[NBLOCKS];

struct LossConsts {
    float V, pmin, patm, pcrit;
    float invL, invL3;          // 1/(pcrit-patm), cubed
    float afr;                  // air_fraction/(1-air_fraction)
    float inv_poly, poly;       // 1/n, n
    float neg_exp;              // -1 - 1/beta_gain
    float betaL, inv_betaL;
    float bg_over_betaL;        // beta_gain/beta_L
    float rho_init;             // rho_L + rho_g*afr
};

__device__ __forceinline__ float loss_elem(float oP, float tP, float dp, float md,
                                           const LossConsts& c)
{
    float p  = 0.1f * oP;
    float pu = fmaxf(p, c.pmin);

    float theta, dtheta;
    if (pu <= c.patm)       { theta = 1.f; dtheta = 0.f; }
    else if (pu >= c.pcrit) { theta = 0.f; dtheta = 0.f; }
    else {
        float x = (pu - c.patm) * c.invL;
        theta  = 1.f - x * x * (3.f - 2.f * x);
        dtheta = 6.f * (pu - c.patm) * (pu - c.pcrit) * c.invL3;
    }

    float rpu = __fdividef(1.f, pu);
    float pr  = __powf(c.patm * rpu, c.inv_poly);
    float a   = c.afr * pr;
    float p_denom = a * theta;
    float p_ratio = a * (theta * rpu * c.inv_poly - dtheta);

    float base     = fmaf(c.bg_over_betaL, pu - c.patm, 1.f);
    float exp_term = __powf(base, c.neg_exp) * c.inv_betaL;

    float denom = fmaf(c.betaL * exp_term, base, p_denom);
    float rd    = __fdividef(1.f, denom);
    float drho  = c.rho_init * (exp_term + p_ratio) * rd * rd;

    float lp  = fabsf(fmaf(c.V * drho, dp, -md));
    float per = fabsf(oP - tP) + 1.9f * lp;
    return (fabsf(dp) >= 1e-12f) ? per : 0.f;
}

__global__ void __launch_bounds__(TPB)
k_loss(const float4* __restrict__ tP4, const float4* __restrict__ dp4,
       const float4* __restrict__ md4, const float4* __restrict__ oP4,
       const float* __restrict__ sV,
       const float* __restrict__ sRhoL, const float* __restrict__ sBetaL,
       const float* __restrict__ sBg,   const float* __restrict__ sAf,
       const float* __restrict__ sRhoG, const float* __restrict__ sPoly,
       const float* __restrict__ sPatm, const float* __restrict__ sPcrit,
       const float* __restrict__ sPmin, int n4)
{
    LossConsts c;
    {
        float V = *sV, rhoL = *sRhoL, betaL = *sBetaL, bg = *sBg, af = *sAf;
        float rhoG = *sRhoG, poly = *sPoly, patm = *sPatm, pcrit = *sPcrit, pmin = *sPmin;
        c.V = V; c.pmin = pmin; c.patm = patm; c.pcrit = pcrit;
        float L = pcrit - patm;
        c.invL  = 1.f / L;
        c.invL3 = c.invL * c.invL * c.invL;
        c.afr   = af / (1.f - af);
        c.poly  = poly;
        c.inv_poly = 1.f / poly;
        c.neg_exp  = -1.f - 1.f / bg;
        c.betaL    = betaL;
        c.inv_betaL = 1.f / betaL;
        c.bg_over_betaL = bg / betaL;
        c.rho_init = rhoL + rhoG * c.afr;
    }

    float acc = 0.f;
    int stride = gridDim.x * blockDim.x;
    for (int i = blockIdx.x * blockDim.x + threadIdx.x; i < n4; i += stride) {
        float4 o = oP4[i];
        float4 t = tP4[i];
        float4 d = dp4[i];
        float4 m = md4[i];
        acc += loss_elem(o.x, t.x, d.x, m.x, c);
        acc += loss_elem(o.y, t.y, d.y, m.y, c);
        acc += loss_elem(o.z, t.z, d.z, m.z, c);
        acc += loss_elem(o.w, t.w, d.w, m.w, c);
    }

    // warp reduce (float), then block reduce in double
    #pragma unroll
    for (int off = 16; off; off >>= 1)
        acc += __shfl_xor_sync(0xffffffffu, acc, off);

    __shared__ double s_warp[TPB / 32];
    if ((threadIdx.x & 31) == 0)
        s_warp[threadIdx.x >> 5] = (double)acc;
    __syncthreads();
    if (threadIdx.x == 0) {
        double b = 0.0;
        #pragma unroll
        for (int w = 0; w < TPB / 32; w++) b += s_warp[w];
        g_partials[blockIdx.x] = b;
    }
}

__global__ void k_reduce(float* __restrict__ out)
{
    __shared__ double sh[256];
    double s = 0.0;
    for (int i = threadIdx.x; i < NBLOCKS; i += 256)
        s += g_partials[i];
    sh[threadIdx.x] = s;
    __syncthreads();
    #pragma unroll
    for (int off = 128; off; off >>= 1) {
        if (threadIdx.x < off) sh[threadIdx.x] += sh[threadIdx.x + off];
        __syncthreads();
    }
    if (threadIdx.x == 0) *out = (float)sh[0];
}

extern "C" void kernel_launch(void* const* d_in, const int* in_sizes, int n_in,
                              void* d_out, int out_size)
{
    const float4* tP4 = (const float4*)d_in[0];   // targets_P
    const float4* dp4 = (const float4*)d_in[1];   // dpdt
    const float4* md4 = (const float4*)d_in[2];   // mdot_A
    const float*  sV  = (const float*)d_in[3];    // V
    const float4* oP4 = (const float4*)d_in[4];   // outputs_P
    const float*  sRhoL  = (const float*)d_in[5];
    const float*  sBetaL = (const float*)d_in[6];
    const float*  sBg    = (const float*)d_in[7];
    const float*  sAf    = (const float*)d_in[8];
    const float*  sRhoG  = (const float*)d_in[9];
    const float*  sPoly  = (const float*)d_in[10];
    const float*  sPatm  = (const float*)d_in[11];
    const float*  sPcrit = (const float*)d_in[12];
    const float*  sPmin  = (const float*)d_in[13];

    int n  = in_sizes[0];
    int n4 = n / 4;   // N = 8,000,000 is divisible by 4

    k_loss<<<NBLOCKS, TPB>>>(tP4, dp4, md4, oP4, sV, sRhoL, sBetaL, sBg, sAf,
                             sRhoG, sPoly, sPatm, sPcrit, sPmin, n4);
    k_reduce<<<1, 256>>>((float*)d_out);
}

// round 2
// speedup vs baseline: 1.4093x; 1.4093x over previous
#include <cuda_runtime.h>

// ---------------------------------------------------------------------------
// My_loss: masked sum over N of  |oP - tP| + 1.9*|V*drho_mix_dp(0.1*oP)*dpdt - mdot|
// Single persistent-grid kernel: streaming reduce + last-block finish.
// ---------------------------------------------------------------------------

#define TPB     256
#define NBLOCKS 1184   // 148 SMs x 8 blocks -> exactly one wave

__device__ double       g_acc    = 0.0;
__device__ unsigned int g_ticket = 0u;

struct LossConsts {
    float V, pmin, patm, pcrit;
    float invL3;                // 1/(pcrit-patm)^3
    float afr;                  // air_fraction/(1-air_fraction)
    float inv_poly;             // 1/n
    float neg_exp;              // -1 - 1/beta_gain
    float betaL, inv_betaL;
    float bg_over_betaL;        // beta_gain/beta_L
    float rho_init;             // rho_L + rho_g*afr
};

__device__ __forceinline__ float loss_elem(float oP, float tP, float dp, float md,
                                           const LossConsts& c)
{
    float p  = 0.1f * oP;
    float pu = fmaxf(p, c.pmin);

    // smoothstep theta + derivative (branch-free via predication)
    float dpa = pu - c.patm;
    float dpc = pu - c.pcrit;
    bool  mid = (pu > c.patm) & (pu < c.pcrit);
    float x   = dpa * (c.invL3) * ((c.pcrit - c.patm) * (c.pcrit - c.patm)); // dpa/L
    float theta  = mid ? (1.f - x * x * (3.f - 2.f * x)) : (pu <= c.patm ? 1.f : 0.f);
    float dtheta = mid ? (6.f * dpa * dpc * c.invL3) : 0.f;

    float rpu = __fdividef(1.f, pu);
    float pr  = __powf(c.patm * rpu, c.inv_poly);
    float a   = c.afr * pr;
    float p_denom = a * theta;
    float p_ratio = a * (theta * rpu * c.inv_poly - dtheta);

    float base     = fmaf(c.bg_over_betaL, dpa, 1.f);
    float exp_term = __powf(base, c.neg_exp) * c.inv_betaL;

    float denom = fmaf(c.betaL * exp_term, base, p_denom);
    float rd    = __fdividef(1.f, denom);
    float drho  = c.rho_init * (exp_term + p_ratio) * rd * rd;

    float lp  = fabsf(fmaf(c.V * drho, dp, -md));
    float per = fabsf(oP - tP) + 1.9f * lp;
    return (fabsf(dp) >= 1e-12f) ? per : 0.f;
}

__global__ void __launch_bounds__(TPB)
k_loss(const float4* __restrict__ tP4, const float4* __restrict__ dp4,
       const float4* __restrict__ md4, const float4* __restrict__ oP4,
       const float* __restrict__ sV,
       const float* __restrict__ sRhoL, const float* __restrict__ sBetaL,
       const float* __restrict__ sBg,   const float* __restrict__ sAf,
       const float* __restrict__ sRhoG, const float* __restrict__ sPoly,
       const float* __restrict__ sPatm, const float* __restrict__ sPcrit,
       const float* __restrict__ sPmin, int n4, float* __restrict__ out)
{
    __shared__ LossConsts sc;
    if (threadIdx.x == 0) {
        float V = *sV, rhoL = *sRhoL, betaL = *sBetaL, bg = *sBg, af = *sAf;
        float rhoG = *sRhoG, poly = *sPoly, patm = *sPatm, pcrit = *sPcrit, pmin = *sPmin;
        sc.V = V; sc.pmin = pmin; sc.patm = patm; sc.pcrit = pcrit;
        float L = pcrit - patm;
        float invL = 1.f / L;
        sc.invL3 = invL * invL * invL;
        sc.afr   = af / (1.f - af);
        sc.inv_poly = 1.f / poly;
        sc.neg_exp  = -1.f - 1.f / bg;
        sc.betaL    = betaL;
        sc.inv_betaL = 1.f / betaL;
        sc.bg_over_betaL = bg / betaL;
        sc.rho_init = rhoL + rhoG * sc.afr;
    }
    __syncthreads();
    const LossConsts c = sc;

    float acc = 0.f;
    const int stride = gridDim.x * blockDim.x;
    #pragma unroll 2
    for (int i = blockIdx.x * blockDim.x + threadIdx.x; i < n4; i += stride) {
        float4 o = oP4[i];
        float4 t = tP4[i];
        float4 d = dp4[i];
        float4 m = md4[i];
        acc += loss_elem(o.x, t.x, d.x, m.x, c);
        acc += loss_elem(o.y, t.y, d.y, m.y, c);
        acc += loss_elem(o.z, t.z, d.z, m.z, c);
        acc += loss_elem(o.w, t.w, d.w, m.w, c);
    }

    // warp reduce (float), then block reduce in double
    #pragma unroll
    for (int off = 16; off; off >>= 1)
        acc += __shfl_xor_sync(0xffffffffu, acc, off);

    __shared__ double s_warp[TPB / 32];
    if ((threadIdx.x & 31) == 0)
        s_warp[threadIdx.x >> 5] = (double)acc;
    __syncthreads();

    if (threadIdx.x == 0) {
        double b = 0.0;
        #pragma unroll
        for (int w = 0; w < TPB / 32; w++) b += s_warp[w];

        atomicAdd(&g_acc, b);
        __threadfence();
        unsigned int t = atomicAdd(&g_ticket, 1u);
        if (t == (unsigned int)(gridDim.x - 1)) {
            // all block partials are in g_acc (each add happened-before its
            // ticket increment via the threadfence above)
            double total = *((volatile double*)&g_acc);
            *out = (float)total;
            // reset state for the next (graph-replayed) invocation
            *((volatile double*)&g_acc) = 0.0;
            __threadfence();
            *((volatile unsigned int*)&g_ticket) = 0u;
        }
    }
}

extern "C" void kernel_launch(void* const* d_in, const int* in_sizes, int n_in,
                              void* d_out, int out_size)
{
    const float4* tP4 = (const float4*)d_in[0];   // targets_P
    const float4* dp4 = (const float4*)d_in[1];   // dpdt
    const float4* md4 = (const float4*)d_in[2];   // mdot_A
    const float*  sV  = (const float*)d_in[3];    // V
    const float4* oP4 = (const float4*)d_in[4];   // outputs_P
    const float*  sRhoL  = (const float*)d_in[5];
    const float*  sBetaL = (const float*)d_in[6];
    const float*  sBg    = (const float*)d_in[7];
    const float*  sAf    = (const float*)d_in[8];
    const float*  sRhoG  = (const float*)d_in[9];
    const float*  sPoly  = (const float*)d_in[10];
    const float*  sPatm  = (const float*)d_in[11];
    const float*  sPcrit = (const float*)d_in[12];
    const float*  sPmin  = (const float*)d_in[13];

    int n  = in_sizes[0];
    int n4 = n / 4;   // N = 8,000,000 divisible by 4

    k_loss<<<NBLOCKS, TPB>>>(tP4, dp4, md4, oP4, sV, sRhoL, sBetaL, sBg, sAf,
                             sRhoG, sPoly, sPatm, sPcrit, sPmin, n4,
                             (float*)d_out);
}

// round 3
// speedup vs baseline: 1.8106x; 1.2847x over previous
#include <cuda_runtime.h>

// ---------------------------------------------------------------------------
// My_loss: masked sum over N of  |oP - tP| + 1.9*|V*drho_mix_dp(0.1*oP)*dpdt - mdot|
// Single persistent-grid kernel (one wave @ 6 blocks/SM), fused finish.
// ---------------------------------------------------------------------------

#define TPB     256
#define BPSM    6
#define NBLOCKS (148 * BPSM)   // exactly one wave at the launch_bounds residency

__device__ double       g_acc    = 0.0;
__device__ unsigned int g_ticket = 0u;

__global__ void __launch_bounds__(TPB, BPSM)
k_loss(const float4* __restrict__ tP4, const float4* __restrict__ dp4,
       const float4* __restrict__ md4, const float4* __restrict__ oP4,
       const float* __restrict__ sV,
       const float* __restrict__ sRhoL, const float* __restrict__ sBetaL,
       const float* __restrict__ sBg,   const float* __restrict__ sAf,
       const float* __restrict__ sRhoG, const float* __restrict__ sPoly,
       const float* __restrict__ sPatm, const float* __restrict__ sPcrit,
       const float* __restrict__ sPmin, int n4, float* __restrict__ out)
{
    // ---- per-thread constant setup (uniform across block; ~20 ops once) ----
    const float patm  = __ldg(sPatm);
    const float pcrit = __ldg(sPcrit);
    const float pmin  = __ldg(sPmin);
    const float af    = __ldg(sAf);
    const float poly  = __ldg(sPoly);
    const float bg    = __ldg(sBg);
    const float betaL = __ldg(sBetaL);

    const float invL      = __fdividef(1.f, pcrit - patm);
    const float sixInvL   = 6.f * invL;
    const float inv_poly  = __fdividef(1.f, poly);
    const float afr       = __fdividef(af, 1.f - af);
    const float Ca        = afr * __powf(patm, inv_poly);      // afr * patm^(1/n)
    const float neg_exp   = -1.f - __fdividef(1.f, bg);
    const float invBetaL  = __fdividef(1.f, betaL);
    const float bgOverBL  = bg * invBetaL;
    const float rhoV      = (__ldg(sRhoL) + __ldg(sRhoG) * afr) * __ldg(sV);

    // ---- streaming loop ----
    float acc = 0.f;
    const int stride = gridDim.x * blockDim.x;
    for (int i = blockIdx.x * blockDim.x + threadIdx.x; i < n4; i += stride) {
        float4 o = oP4[i];
        float4 t = tP4[i];
        float4 d = dp4[i];
        float4 m = md4[i];

        #pragma unroll
        for (int k = 0; k < 4; k++) {
            float oP = (&o.x)[k];
            float tP = (&t.x)[k];
            float dp = (&d.x)[k];
            float md = (&m.x)[k];

            float pu  = fmaxf(0.1f * oP, pmin);
            float dpa = pu - patm;

            // branch-free smoothstep: clamp makes boundary cases exact
            float x      = __saturatef(dpa * invL);
            float theta  = fmaf(x * x, fmaf(2.f, x, -3.f), 1.f);   // 1 + x^2(2x-3)
            float dtheta = sixInvL * x * (x - 1.f);

            float rpu = __fdividef(1.f, pu);
            float pr  = Ca * __powf(pu, -inv_poly);                // afr*(patm/pu)^(1/n)
            float p_denom = pr * theta;
            float p_ratio = pr * fmaf(theta * rpu, inv_poly, -dtheta);

            float base = fmaf(bgOverBL, dpa, 1.f);
            float g1   = __powf(base, neg_exp);                    // base^(-1-1/bg)
            float exp_term = g1 * invBetaL;
            float denom    = fmaf(g1, base, p_denom);              // base^(-1/bg) + p_denom

            float rd   = __fdividef(1.f, denom);
            float drho = rhoV * (exp_term + p_ratio) * rd * rd;    // includes V

            float lp  = fabsf(fmaf(drho, dp, -md));
            float per = fabsf(oP - tP) + 1.9f * lp;
            acc += (fabsf(dp) >= 1e-12f) ? per : 0.f;
        }
    }

    // ---- warp reduce (float), block reduce (double), global finish ----
    #pragma unroll
    for (int off = 16; off; off >>= 1)
        acc += __shfl_xor_sync(0xffffffffu, acc, off);

    __shared__ double s_warp[TPB / 32];
    if ((threadIdx.x & 31) == 0)
        s_warp[threadIdx.x >> 5] = (double)acc;
    __syncthreads();

    if (threadIdx.x == 0) {
        double b = 0.0;
        #pragma unroll
        for (int w = 0; w < TPB / 32; w++) b += s_warp[w];

        atomicAdd(&g_acc, b);
        __threadfence();
        unsigned int tkt = atomicAdd(&g_ticket, 1u);
        if (tkt == (unsigned int)(gridDim.x - 1)) {
            double total = *((volatile double*)&g_acc);
            *out = (float)total;
            *((volatile double*)&g_acc) = 0.0;
            __threadfence();
            *((volatile unsigned int*)&g_ticket) = 0u;
        }
    }
}

extern "C" void kernel_launch(void* const* d_in, const int* in_sizes, int n_in,
                              void* d_out, int out_size)
{
    const float4* tP4 = (const float4*)d_in[0];   // targets_P
    const float4* dp4 = (const float4*)d_in[1];   // dpdt
    const float4* md4 = (const float4*)d_in[2];   // mdot_A
    const float*  sV  = (const float*)d_in[3];    // V
    const float4* oP4 = (const float4*)d_in[4];   // outputs_P
    const float*  sRhoL  = (const float*)d_in[5];
    const float*  sBetaL = (const float*)d_in[6];
    const float*  sBg    = (const float*)d_in[7];
    const float*  sAf    = (const float*)d_in[8];
    const float*  sRhoG  = (const float*)d_in[9];
    const float*  sPoly  = (const float*)d_in[10];
    const float*  sPatm  = (const float*)d_in[11];
    const float*  sPcrit = (const float*)d_in[12];
    const float*  sPmin  = (const float*)d_in[13];

    int n  = in_sizes[0];
    int n4 = n / 4;   // N = 8,000,000 divisible by 4

    k_loss<<<NBLOCKS, TPB>>>(tP4, dp4, md4, oP4, sV, sRhoL, sBetaL, sBg, sAf,
                             sRhoG, sPoly, sPatm, sPcrit, sPmin, n4,
                             (float*)d_out);
}